// round 8
// baseline (speedup 1.0000x reference)
#include <cuda_runtime.h>
#include <cstdint>

#define D_MODEL 1024
#define N_HEADS 16
#define DK 64
#define BATCH 2
#define MAX_S 4096
#define D2 (D_MODEL * D_MODEL)

// Scratch: __device__ globals (allocation inside kernel_launch is forbidden).
__device__ float    g_Q [BATCH * MAX_S * D_MODEL];
__device__ float    g_K [BATCH * MAX_S * D_MODEL];
__device__ float    g_V [BATCH * MAX_S * D_MODEL];
__device__ float    g_AO[BATCH * MAX_S * D_MODEL];
__device__ uint32_t g_Wt[4 * D2];                    // tf32 bits, 4 weights

// ---------------------------------------------------------------------------
// Helpers
// ---------------------------------------------------------------------------
__device__ __forceinline__ float ex2f(float x) {
    float y; asm("ex2.approx.ftz.f32 %0, %1;" : "=f"(y) : "f"(x)); return y;
}
__device__ __forceinline__ uint32_t f2tf32(float x) {
    uint32_t r; asm("cvt.rna.tf32.f32 %0, %1;" : "=r"(r) : "f"(x)); return r;
}
__device__ __forceinline__ uint32_t smem_to_u32(const void* p) {
    uint32_t a;
    asm("{ .reg .u64 t; cvta.to.shared.u64 t, %1; cvt.u32.u64 %0, t; }"
        : "=r"(a) : "l"(p));
    return a;
}
#define CP_ASYNC16(dst, src) \
    asm volatile("cp.async.cg.shared.global [%0], [%1], 16;" \
        :: "r"(dst), "l"(src) : "memory")
#define CP_COMMIT()  asm volatile("cp.async.commit_group;" ::: "memory")
#define CP_WAIT1()   asm volatile("cp.async.wait_group 1;" ::: "memory")

// mma.sync m16n8k8 tf32 (sm_80+, portable target): D += A*B, fp32 accum.
#define MMA_TF32(c, a, b0, b1) \
    asm volatile("mma.sync.aligned.m16n8k8.row.col.f32.tf32.tf32.f32 " \
        "{%0,%1,%2,%3}, {%4,%5,%6,%7}, {%8,%9}, {%0,%1,%2,%3};" \
        : "+f"((c)[0]), "+f"((c)[1]), "+f"((c)[2]), "+f"((c)[3]) \
        : "r"((a)[0]), "r"((a)[1]), "r"((a)[2]), "r"((a)[3]), \
          "r"(b0), "r"(b1))

// ---------------------------------------------------------------------------
// Convert all four weight matrices to tf32 bits in one launch.
// ---------------------------------------------------------------------------
__global__ void cvt_w4_kernel(const float* __restrict__ W0,
                              const float* __restrict__ W1,
                              const float* __restrict__ W2,
                              const float* __restrict__ W3,
                              uint32_t* __restrict__ Wt)
{
    const float* W = (blockIdx.y == 0) ? W0 : (blockIdx.y == 1) ? W1
                   : (blockIdx.y == 2) ? W2 : W3;
    int i = blockIdx.x * 256 + threadIdx.x;
    float4 w = ((const float4*)W)[i];
    uint4 t;
    t.x = f2tf32(w.x); t.y = f2tf32(w.y); t.z = f2tf32(w.z); t.w = f2tf32(w.w);
    ((uint4*)(Wt + (size_t)blockIdx.y * D2))[i] = t;
}

// ---------------------------------------------------------------------------
// Projection GEMM v3: C[M,N] = A[M,K] @ Wt[N,K]^T + bias, A split to
// (hi,lo) tf32 INLINE at fragment-load time (bit-identical to the former
// split kernel: hi = rna(a), lo = rna(a - hi); 2 MMA passes, fp32 accum).
// 128x128 tile, BK=32, 256 threads = 8 warps (4x2); warp tile 32x64.
// 3-stage cp.async pipeline (A fp32 + W tf32, 32KB/stage, 96KB total);
// XOR-swizzled tiles => conflict-free fragment LDS.
// ---------------------------------------------------------------------------
#define GEMM_SMEM (3 * 32768)

// element index of (r, c) in a swizzled 128x32 tile (u32/f32 elements).
__device__ __forceinline__ int sidx(int r, int c) {
    return r * 32 + ((((c >> 2) ^ (r & 7))) << 2) + (c & 3);
}

__global__ __launch_bounds__(256, 2)
void gemm_tf32_kernel(const float* __restrict__ A,
                      const uint32_t* __restrict__ Wt,
                      const float* __restrict__ bias, float* __restrict__ C,
                      int M, int N, int K)
{
    extern __shared__ uint32_t sm[];
    const uint32_t sbase = smem_to_u32(sm);

    const int tid  = threadIdx.x;
    const int wid  = tid >> 5;
    const int lane = tid & 31;
    const int gr   = lane >> 2;
    const int tig  = lane & 3;
    const int m0 = blockIdx.y * 128;
    const int n0 = blockIdx.x * 128;
    const int wm = (wid >> 1) * 32;
    const int wn = (wid & 1) * 64;

    // Per-thread copy slice: 4 (row, seg) pairs per tile per stage.
    const int cr0 = tid >> 3;        // rows tid/8 + {0,32,64,96}
    const int cs  = tid & 7;         // 16B segment 0..7

    float c[2][8][4];
    #pragma unroll
    for (int mt = 0; mt < 2; mt++)
        #pragma unroll
        for (int nn = 0; nn < 8; nn++)
            #pragma unroll
            for (int j = 0; j < 4; j++) c[mt][nn][j] = 0.0f;

    // Issue one stage (A fp32 tile + W tf32 tile) into buffer `buf`.
    auto issue = [&](int k0, int buf) {
        const uint32_t base = sbase + buf * 32768;
        #pragma unroll
        for (int j = 0; j < 4; j++) {
            int r = cr0 + j * 32;
            uint32_t sw = (uint32_t)(r * 128 + ((cs ^ (r & 7)) << 4));
            const float*    sA = A  + (size_t)(m0 + r) * K + k0 + cs * 4;
            const uint32_t* sW = Wt + (size_t)(n0 + r) * K + k0 + cs * 4;
            CP_ASYNC16(base + sw,         sA);
            CP_ASYNC16(base + 16384 + sw, sW);
        }
        CP_COMMIT();
    };

    issue(0, 0);
    issue(32, 1);

    int buf = 0;
    for (int k0 = 0; k0 < K; k0 += 32) {
        CP_WAIT1();
        __syncthreads();
        if (k0 + 64 < K) issue(k0 + 64, (buf + 2) % 3);

        const float*    Ab = (const float*)(sm + buf * 8192);
        const uint32_t* Wb = sm + buf * 8192 + 4096;

        #pragma unroll
        for (int kk = 0; kk < 4; kk++) {
            const int kb = kk * 8;
            uint32_t bf0[8], bf1[8];
            #pragma unroll
            for (int nn = 0; nn < 8; nn++) {
                int rw = wn + nn * 8 + gr;
                bf0[nn] = Wb[sidx(rw, kb + tig)];
                bf1[nn] = Wb[sidx(rw, kb + tig + 4)];
            }
            #pragma unroll
            for (int mt = 0; mt < 2; mt++) {
                const int R  = wm + mt * 16 + gr;
                const int R8 = R + 8;
                float a0 = Ab[sidx(R,  kb + tig)];
                float a1 = Ab[sidx(R8, kb + tig)];
                float a2 = Ab[sidx(R,  kb + tig + 4)];
                float a3 = Ab[sidx(R8, kb + tig + 4)];
                uint32_t ah[4], al[4];
                ah[0] = f2tf32(a0); al[0] = f2tf32(a0 - __uint_as_float(ah[0]));
                ah[1] = f2tf32(a1); al[1] = f2tf32(a1 - __uint_as_float(ah[1]));
                ah[2] = f2tf32(a2); al[2] = f2tf32(a2 - __uint_as_float(ah[2]));
                ah[3] = f2tf32(a3); al[3] = f2tf32(a3 - __uint_as_float(ah[3]));
                #pragma unroll
                for (int nn = 0; nn < 8; nn++) {
                    MMA_TF32(c[mt][nn], ah, bf0[nn], bf1[nn]);
                    MMA_TF32(c[mt][nn], al, bf0[nn], bf1[nn]);
                }
            }
        }
        __syncthreads();
        buf = (buf + 1) % 3;
    }

    // Epilogue: add bias (fp32), store.
    #pragma unroll
    for (int mt = 0; mt < 2; mt++) {
        int R = m0 + wm + mt * 16 + gr;
        #pragma unroll
        for (int nn = 0; nn < 8; nn++) {
            int col = n0 + wn + nn * 8 + tig * 2;
            float2 bv = *(const float2*)(bias + col);
            float2 v0; v0.x = c[mt][nn][0] + bv.x; v0.y = c[mt][nn][1] + bv.y;
            float2 v1; v1.x = c[mt][nn][2] + bv.x; v1.y = c[mt][nn][3] + bv.y;
            *(float2*)(C + (size_t)R * N + col) = v0;
            *(float2*)(C + (size_t)(R + 8) * N + col) = v1;
        }
    }
}

// ---------------------------------------------------------------------------
// Flash attention via mma.sync m16n8k8 tf32 — 4 warps x 32 q-rows.
// (Math identical to Rounds 5-7, passing at rel_err ~6.77e-4 overall;
//  plain fp32 AO output.)
// ---------------------------------------------------------------------------
__global__ __launch_bounds__(128, 2)
void flash_mma_kernel(const float* __restrict__ Q, const float* __restrict__ K,
                      const float* __restrict__ V, float* __restrict__ O, int S)
{
    __shared__ uint32_t Kt[64 * 68];
    __shared__ uint32_t Vs[64 * 68];

    const int tid  = threadIdx.x;
    const int wid  = tid >> 5;           // 0..3
    const int lane = tid & 31;
    const int gr   = lane >> 2;
    const int tig  = lane & 3;

    const int q0 = blockIdx.x * 128;
    const int b  = blockIdx.y >> 4;
    const int h  = blockIdx.y & 15;
    const int m0 = wid * 32;             // warp's q-row base within tile

    const float* Qb = Q + ((size_t)b * S + q0) * D_MODEL + h * DK;
    const float* Kb = K + (size_t)b * S * D_MODEL + h * DK;
    const float* Vb = V + (size_t)b * S * D_MODEL + h * DK;

    // Q fragments (2 m16 tiles): fold 1/sqrt(dk) * log2(e) for ex2 softmax.
    const float QSCALE = 0.125f * 1.4426950408889634f;
    uint32_t qf[8][8];
    #pragma unroll
    for (int kk = 0; kk < 8; kk++) {
        const int c0 = kk * 8 + tig;
        qf[kk][0] = f2tf32(Qb[(size_t)(m0 + gr)      * D_MODEL + c0]     * QSCALE);
        qf[kk][1] = f2tf32(Qb[(size_t)(m0 + gr + 8)  * D_MODEL + c0]     * QSCALE);
        qf[kk][2] = f2tf32(Qb[(size_t)(m0 + gr)      * D_MODEL + c0 + 4] * QSCALE);
        qf[kk][3] = f2tf32(Qb[(size_t)(m0 + gr + 8)  * D_MODEL + c0 + 4] * QSCALE);
        qf[kk][4] = f2tf32(Qb[(size_t)(m0 + gr + 16) * D_MODEL + c0]     * QSCALE);
        qf[kk][5] = f2tf32(Qb[(size_t)(m0 + gr + 24) * D_MODEL + c0]     * QSCALE);
        qf[kk][6] = f2tf32(Qb[(size_t)(m0 + gr + 16) * D_MODEL + c0 + 4] * QSCALE);
        qf[kk][7] = f2tf32(Qb[(size_t)(m0 + gr + 24) * D_MODEL + c0 + 4] * QSCALE);
    }

    float m_g[4], l_g[4];
    #pragma unroll
    for (int g = 0; g < 4; g++) { m_g[g] = -1e30f; l_g[g] = 0.0f; }
    float o[8][8];
    #pragma unroll
    for (int nn = 0; nn < 8; nn++)
        #pragma unroll
        for (int j = 0; j < 8; j++) o[nn][j] = 0.0f;

    const int srcA = (lane & 28) | (tig >> 1);  // source lane for col tig
    const int srcB = srcA + 2;                  // source lane for col tig+4
    const bool sel = (tig & 1) != 0;

    const int nkb = S >> 6;
    for (int kb = 0; kb < nkb; kb++) {
        __syncthreads();
        // Cooperative K/V tile load (64 x 64), tf32-rounded, pad-68 rows.
        #pragma unroll
        for (int i = 0; i < 8; i++) {
            int idx = tid + i * 128;
            int r = idx >> 4, c4 = idx & 15;
            float4 k4 = *(const float4*)(Kb + (size_t)(kb*64 + r) * D_MODEL + c4*4);
            uint4 ku; ku.x = f2tf32(k4.x); ku.y = f2tf32(k4.y);
                      ku.z = f2tf32(k4.z); ku.w = f2tf32(k4.w);
            *(uint4*)&Kt[r * 68 + c4 * 4] = ku;
            float4 v4 = *(const float4*)(Vb + (size_t)(kb*64 + r) * D_MODEL + c4*4);
            uint4 vu; vu.x = f2tf32(v4.x); vu.y = f2tf32(v4.y);
                      vu.z = f2tf32(v4.z); vu.w = f2tf32(v4.w);
            *(uint4*)&Vs[r * 68 + c4 * 4] = vu;
        }
        __syncthreads();

        // ---- S = Q @ K^T : warp computes 32 x 64 scores ----
        float sv[8][8];
        #pragma unroll
        for (int nn = 0; nn < 8; nn++) {
            #pragma unroll
            for (int j = 0; j < 8; j++) sv[nn][j] = 0.0f;
            #pragma unroll
            for (int kk = 0; kk < 8; kk++) {
                uint32_t b0 = Kt[(nn*8 + gr) * 68 + kk*8 + tig];
                uint32_t b1 = Kt[(nn*8 + gr) * 68 + kk*8 + tig + 4];
                MMA_TF32(&sv[nn][0], &qf[kk][0], b0, b1);   // rows m0..m0+16
                MMA_TF32(&sv[nn][4], &qf[kk][4], b0, b1);   // rows m0+16..m0+32
            }
        }

        // ---- online softmax: 4 row groups, quad-local reductions ----
        float al[4];
        #pragma unroll
        for (int g = 0; g < 4; g++) {
            float mx = -1e30f;
            #pragma unroll
            for (int nn = 0; nn < 8; nn++)
                mx = fmaxf(mx, fmaxf(sv[nn][2*g], sv[nn][2*g+1]));
            mx = fmaxf(mx, __shfl_xor_sync(0xffffffffu, mx, 1));
            mx = fmaxf(mx, __shfl_xor_sync(0xffffffffu, mx, 2));
            float mn = fmaxf(m_g[g], mx);
            al[g] = ex2f(m_g[g] - mn);
            m_g[g] = mn;
            float rs = 0.0f;
            #pragma unroll
            for (int nn = 0; nn < 8; nn++) {
                sv[nn][2*g]   = ex2f(sv[nn][2*g]   - mn);
                sv[nn][2*g+1] = ex2f(sv[nn][2*g+1] - mn);
                rs += sv[nn][2*g] + sv[nn][2*g+1];
            }
            rs += __shfl_xor_sync(0xffffffffu, rs, 1);
            rs += __shfl_xor_sync(0xffffffffu, rs, 2);
            l_g[g] = l_g[g] * al[g] + rs;
        }
        #pragma unroll
        for (int nn = 0; nn < 8; nn++)
            #pragma unroll
            for (int g = 0; g < 4; g++) {
                o[nn][2*g]   *= al[g];
                o[nn][2*g+1] *= al[g];
            }

        // ---- O += P @ V : P C-frags -> A-frags via shuffles ----
        #pragma unroll
        for (int kk = 0; kk < 8; kk++) {
            uint32_t a[8];
            #pragma unroll
            for (int t = 0; t < 2; t++) {
                float v00 = __shfl_sync(0xffffffffu, sv[kk][t*4+0], srcA);
                float v01 = __shfl_sync(0xffffffffu, sv[kk][t*4+1], srcA);
                float v10 = __shfl_sync(0xffffffffu, sv[kk][t*4+2], srcA);
                float v11 = __shfl_sync(0xffffffffu, sv[kk][t*4+3], srcA);
                float w00 = __shfl_sync(0xffffffffu, sv[kk][t*4+0], srcB);
                float w01 = __shfl_sync(0xffffffffu, sv[kk][t*4+1], srcB);
                float w10 = __shfl_sync(0xffffffffu, sv[kk][t*4+2], srcB);
                float w11 = __shfl_sync(0xffffffffu, sv[kk][t*4+3], srcB);
                a[t*4+0] = __float_as_uint(sel ? v01 : v00);
                a[t*4+1] = __float_as_uint(sel ? v11 : v10);
                a[t*4+2] = __float_as_uint(sel ? w01 : w00);
                a[t*4+3] = __float_as_uint(sel ? w11 : w10);
            }
            #pragma unroll
            for (int nn = 0; nn < 8; nn++) {
                uint32_t b0 = Vs[(kk*8 + tig)     * 68 + nn*8 + gr];
                uint32_t b1 = Vs[(kk*8 + tig + 4) * 68 + nn*8 + gr];
                MMA_TF32(&o[nn][0], &a[0], b0, b1);
                MMA_TF32(&o[nn][4], &a[4], b0, b1);
            }
        }
    }

    // ---- epilogue: normalize, store (layout [B*S, D_MODEL]) ----
    float inv[4];
    #pragma unroll
    for (int g = 0; g < 4; g++) inv[g] = 1.0f / l_g[g];
    float* Ob = O + ((size_t)b * S + q0) * D_MODEL + h * DK;
    const int rowg[4] = { m0 + gr, m0 + gr + 8, m0 + gr + 16, m0 + gr + 24 };
    #pragma unroll
    for (int nn = 0; nn < 8; nn++) {
        #pragma unroll
        for (int g = 0; g < 4; g++) {
            float2 val;
            val.x = o[nn][2*g]   * inv[g];
            val.y = o[nn][2*g+1] * inv[g];
            *(float2*)(Ob + (size_t)rowg[g] * D_MODEL + nn*8 + tig*2) = val;
        }
    }
}

// ---------------------------------------------------------------------------
extern "C" void kernel_launch(void* const* d_in, const int* in_sizes, int n_in,
                              void* d_out, int out_size)
{
    (void)n_in; (void)out_size;
    const float* query = (const float*)d_in[0];
    const float* key   = (const float*)d_in[1];
    const float* value = (const float*)d_in[2];
    const float* Wq = (const float*)d_in[3];
    const float* bq = (const float*)d_in[4];
    const float* Wk = (const float*)d_in[5];
    const float* bk = (const float*)d_in[6];
    const float* Wv = (const float*)d_in[7];
    const float* bv = (const float*)d_in[8];
    const float* Wo = (const float*)d_in[9];
    const float* bo = (const float*)d_in[10];
    float* out = (float*)d_out;

    const int M = in_sizes[0] / D_MODEL;   // B*S = 8192
    const int S = M / BATCH;               // 4096

    float *pQ, *pK, *pV, *pAO;
    uint32_t *pWt;
    cudaGetSymbolAddress((void**)&pQ,  g_Q);
    cudaGetSymbolAddress((void**)&pK,  g_K);
    cudaGetSymbolAddress((void**)&pV,  g_V);
    cudaGetSymbolAddress((void**)&pAO, g_AO);
    cudaGetSymbolAddress((void**)&pWt, g_Wt);

    cudaFuncSetAttribute(gemm_tf32_kernel,
                         cudaFuncAttributeMaxDynamicSharedMemorySize, GEMM_SMEM);

    const int nw = D2 / 4 / 256;                     // 1024 blocks per weight
    dim3 gblk(D_MODEL / 128, M / 128);               // (8, 64)

    cvt_w4_kernel<<<dim3(nw, 4), 256>>>(Wq, Wk, Wv, Wo, pWt);

    gemm_tf32_kernel<<<gblk, 256, GEMM_SMEM>>>(query, pWt,          bq, pQ, M, D_MODEL, D_MODEL);
    gemm_tf32_kernel<<<gblk, 256, GEMM_SMEM>>>(key,   pWt + D2,     bk, pK, M, D_MODEL, D_MODEL);
    gemm_tf32_kernel<<<gblk, 256, GEMM_SMEM>>>(value, pWt + 2 * D2, bv, pV, M, D_MODEL, D_MODEL);

    flash_mma_kernel<<<dim3(S / 128, BATCH * N_HEADS), 128>>>(pQ, pK, pV, pAO, S);

    gemm_tf32_kernel<<<gblk, 256, GEMM_SMEM>>>(pAO, pWt + 3 * D2, bo, out, M, D_MODEL, D_MODEL);
}

// round 9
// speedup vs baseline: 1.1557x; 1.1557x over previous
#include <cuda_runtime.h>
#include <cuda_bf16.h>
#include <cstdint>

#define D_MODEL 1024
#define N_HEADS 16
#define DK 64
#define BATCH 2
#define MAX_S 4096
#define D2 (D_MODEL * D_MODEL)
#define HW (D2 / 2)

// Scratch: __device__ globals (allocation inside kernel_launch is forbidden).
__device__ float    g_Q  [BATCH * MAX_S * D_MODEL];
__device__ float    g_K  [BATCH * MAX_S * D_MODEL];
__device__ float    g_V  [BATCH * MAX_S * D_MODEL];
__device__ float    g_AO [BATCH * MAX_S * D_MODEL];
__device__ uint32_t g_Ahi[BATCH * MAX_S * D_MODEL / 2];  // packed bf16 pairs
__device__ uint32_t g_Alo[BATCH * MAX_S * D_MODEL / 2];
__device__ uint32_t g_Whi[4 * HW];
__device__ uint32_t g_Wlo[4 * HW];

// ---------------------------------------------------------------------------
// Helpers
// ---------------------------------------------------------------------------
__device__ __forceinline__ float ex2f(float x) {
    float y; asm("ex2.approx.ftz.f32 %0, %1;" : "=f"(y) : "f"(x)); return y;
}
__device__ __forceinline__ uint32_t f2tf32(float x) {
    uint32_t r; asm("cvt.rna.tf32.f32 %0, %1;" : "=r"(r) : "f"(x)); return r;
}
__device__ __forceinline__ uint32_t smem_to_u32(const void* p) {
    uint32_t a;
    asm("{ .reg .u64 t; cvta.to.shared.u64 t, %1; cvt.u32.u64 %0, t; }"
        : "=r"(a) : "l"(p));
    return a;
}
#define CP_ASYNC16(dst, src) \
    asm volatile("cp.async.cg.shared.global [%0], [%1], 16;" \
        :: "r"(dst), "l"(src) : "memory")
#define CP_COMMIT()  asm volatile("cp.async.commit_group;" ::: "memory")
#define CP_WAIT1()   asm volatile("cp.async.wait_group 1;" ::: "memory")
#define CP_WAIT0()   asm volatile("cp.async.wait_group 0;" ::: "memory")

// mma.sync tf32 m16n8k8 (flash) and bf16 m16n8k16 (projections), fp32 accum.
#define MMA_TF32(c, a, b0, b1) \
    asm volatile("mma.sync.aligned.m16n8k8.row.col.f32.tf32.tf32.f32 " \
        "{%0,%1,%2,%3}, {%4,%5,%6,%7}, {%8,%9}, {%0,%1,%2,%3};" \
        : "+f"((c)[0]), "+f"((c)[1]), "+f"((c)[2]), "+f"((c)[3]) \
        : "r"((a)[0]), "r"((a)[1]), "r"((a)[2]), "r"((a)[3]), \
          "r"(b0), "r"(b1))
#define MMA_BF16(c, a, b0, b1) \
    asm volatile("mma.sync.aligned.m16n8k16.row.col.f32.bf16.bf16.f32 " \
        "{%0,%1,%2,%3}, {%4,%5,%6,%7}, {%8,%9}, {%0,%1,%2,%3};" \
        : "+f"((c)[0]), "+f"((c)[1]), "+f"((c)[2]), "+f"((c)[3]) \
        : "r"((a)[0]), "r"((a)[1]), "r"((a)[2]), "r"((a)[3]), \
          "r"(b0), "r"(b1))
#define LDMX4(r0, r1, r2, r3, addr) \
    asm volatile("ldmatrix.sync.aligned.m8n8.x4.shared.b16 {%0,%1,%2,%3}, [%4];" \
        : "=r"(r0), "=r"(r1), "=r"(r2), "=r"(r3) : "r"(addr))
#define LDMX2(r0, r1, addr) \
    asm volatile("ldmatrix.sync.aligned.m8n8.x2.shared.b16 {%0,%1}, [%2];" \
        : "=r"(r0), "=r"(r1) : "r"(addr))

// Split one float into bf16 (hi, lo): v ~= hi + lo to ~17 mantissa bits.
// Returns packed pair (a in low half, b in high half) for hi; lo via out-param.
__device__ __forceinline__ uint32_t packsplit2(float a, float b, uint32_t& lo) {
    __nv_bfloat16 ha = __float2bfloat16_rn(a);
    __nv_bfloat16 hb = __float2bfloat16_rn(b);
    __nv_bfloat16 la = __float2bfloat16_rn(a - __bfloat162float(ha));
    __nv_bfloat16 lb = __float2bfloat16_rn(b - __bfloat162float(hb));
    __nv_bfloat162 hp; hp.x = ha; hp.y = hb;
    __nv_bfloat162 lp; lp.x = la; lp.y = lb;
    lo = *reinterpret_cast<uint32_t*>(&lp);
    return *reinterpret_cast<uint32_t*>(&hp);
}

// ---------------------------------------------------------------------------
// Split kernels: fp32 -> packed bf16 (hi, lo) planes (k-pairs packed in u32).
// ---------------------------------------------------------------------------
__global__ void split_bf16_kernel(const float* __restrict__ X,
                                  uint32_t* __restrict__ hi,
                                  uint32_t* __restrict__ lo)
{
    int i = blockIdx.x * 256 + threadIdx.x;
    float4 v = ((const float4*)X)[i];
    uint2 h, l;
    h.x = packsplit2(v.x, v.y, l.x);
    h.y = packsplit2(v.z, v.w, l.y);
    ((uint2*)hi)[i] = h;
    ((uint2*)lo)[i] = l;
}

__global__ void split_w4_kernel(const float* __restrict__ W0,
                                const float* __restrict__ W1,
                                const float* __restrict__ W2,
                                const float* __restrict__ W3,
                                uint32_t* __restrict__ Whi,
                                uint32_t* __restrict__ Wlo)
{
    const float* W = (blockIdx.y == 0) ? W0 : (blockIdx.y == 1) ? W1
                   : (blockIdx.y == 2) ? W2 : W3;
    int i = blockIdx.x * 256 + threadIdx.x;
    float4 v = ((const float4*)W)[i];
    uint2 h, l;
    h.x = packsplit2(v.x, v.y, l.x);
    h.y = packsplit2(v.z, v.w, l.y);
    ((uint2*)(Whi + (size_t)blockIdx.y * HW))[i] = h;
    ((uint2*)(Wlo + (size_t)blockIdx.y * HW))[i] = l;
}

// ---------------------------------------------------------------------------
// Projection GEMM v4: C = A @ W^T + bias via bf16 m16n8k16, 3-pass split:
//   C += Ahi*Whi + Ahi*Wlo + Alo*Whi   (dropped Alo*Wlo ~ 2^-16)
// 128x128 tile, 32 k per stage (16 packed pairs), 256 threads = 8 warps (4x2),
// warp tile 32x64. 2-stage cp.async pipeline. Tiles stored [128 rows][20 u32]
// (16 data + 4 pad): row stride 80B makes every 8-row ldmatrix phase hit
// distinct bank groups. Fragments via ldmatrix.x4 (A) / .x2 (W).
// Plane layout per stage: [Ahi | Alo | Whi | Wlo], 2560 u32 each.
// ---------------------------------------------------------------------------
#define GEMM_SMEM (2 * 4 * 2560 * 4)

__global__ __launch_bounds__(256, 2)
void gemm_bf16_kernel(const uint32_t* __restrict__ Ahi,
                      const uint32_t* __restrict__ Alo,
                      const uint32_t* __restrict__ Whi,
                      const uint32_t* __restrict__ Wlo,
                      const float* __restrict__ bias, float* __restrict__ C,
                      int M, int N, int K2)
{
    extern __shared__ uint32_t sm[];
    const uint32_t sbase = smem_to_u32(sm);

    const int tid  = threadIdx.x;
    const int wid  = tid >> 5;
    const int lane = tid & 31;
    const int gr   = lane >> 2;
    const int tig  = lane & 3;
    const int m0 = blockIdx.y * 128;
    const int n0 = blockIdx.x * 128;
    const int wm = (wid >> 1) * 32;
    const int wn = (wid & 1) * 64;

    // copy roles: 64B row-chunks, 4 segs of 16B
    const int crow = tid >> 2;       // 0..63
    const int cseg = tid & 3;

    float c[2][8][4];
    #pragma unroll
    for (int mt = 0; mt < 2; mt++)
        #pragma unroll
        for (int nn = 0; nn < 8; nn++)
            #pragma unroll
            for (int j = 0; j < 4; j++) c[mt][nn][j] = 0.0f;

    auto issue = [&](int kp, int buf) {
        const uint32_t base = sbase + (uint32_t)buf * 40960u;
        #pragma unroll
        for (int it = 0; it < 2; it++) {
            int r = crow + it * 64;
            uint32_t dst = base + (uint32_t)(r * 80 + cseg * 16);
            const uint32_t* sa = Ahi + (size_t)(m0 + r) * K2 + kp + cseg * 4;
            const uint32_t* sl = Alo + (size_t)(m0 + r) * K2 + kp + cseg * 4;
            const uint32_t* sh = Whi + (size_t)(n0 + r) * K2 + kp + cseg * 4;
            const uint32_t* sw = Wlo + (size_t)(n0 + r) * K2 + kp + cseg * 4;
            CP_ASYNC16(dst,           sa);
            CP_ASYNC16(dst + 10240u,  sl);
            CP_ASYNC16(dst + 20480u,  sh);
            CP_ASYNC16(dst + 30720u,  sw);
        }
        CP_COMMIT();
    };

    // ldmatrix per-lane byte offsets within a tile
    const uint32_t a_off = (uint32_t)((((lane & 7) + ((lane >> 3) & 1) * 8) * 80)
                                      + (lane >> 4) * 16);
    const uint32_t w_off = (uint32_t)(((lane & 7) * 80) + ((lane >> 3) & 1) * 16);

    issue(0, 0);

    int buf = 0;
    for (int kp = 0; kp < K2; kp += 16, buf ^= 1) {
        if (kp + 16 < K2) { issue(kp + 16, buf ^ 1); CP_WAIT1(); }
        else              { CP_WAIT0(); }
        __syncthreads();

        const uint32_t stA_hi = sbase + (uint32_t)buf * 40960u;
        const uint32_t stA_lo = stA_hi + 10240u;
        const uint32_t stW_hi = stA_hi + 20480u;
        const uint32_t stW_lo = stA_hi + 30720u;

        #pragma unroll
        for (int kk = 0; kk < 2; kk++) {
            const uint32_t kbb = (uint32_t)kk * 32u;   // 8 pair-cols * 4B
            uint32_t wh0[8], wh1[8], wl0[8], wl1[8];
            #pragma unroll
            for (int nn = 0; nn < 8; nn++) {
                uint32_t wb = (uint32_t)((wn + nn * 8) * 80) + w_off + kbb;
                LDMX2(wh0[nn], wh1[nn], stW_hi + wb);
                LDMX2(wl0[nn], wl1[nn], stW_lo + wb);
            }
            #pragma unroll
            for (int mt = 0; mt < 2; mt++) {
                uint32_t ab = (uint32_t)((wm + mt * 16) * 80) + a_off + kbb;
                uint32_t ah[4], al[4];
                LDMX4(ah[0], ah[1], ah[2], ah[3], stA_hi + ab);
                LDMX4(al[0], al[1], al[2], al[3], stA_lo + ab);
                #pragma unroll
                for (int nn = 0; nn < 8; nn++) {
                    MMA_BF16(c[mt][nn], ah, wh0[nn], wh1[nn]);
                    MMA_BF16(c[mt][nn], ah, wl0[nn], wl1[nn]);
                    MMA_BF16(c[mt][nn], al, wh0[nn], wh1[nn]);
                }
            }
        }
        __syncthreads();
    }

    // Epilogue: add bias (fp32), store.
    #pragma unroll
    for (int mt = 0; mt < 2; mt++) {
        int R = m0 + wm + mt * 16 + gr;
        #pragma unroll
        for (int nn = 0; nn < 8; nn++) {
            int col = n0 + wn + nn * 8 + tig * 2;
            float2 bv = *(const float2*)(bias + col);
            float2 v0; v0.x = c[mt][nn][0] + bv.x; v0.y = c[mt][nn][1] + bv.y;
            float2 v1; v1.x = c[mt][nn][2] + bv.x; v1.y = c[mt][nn][3] + bv.y;
            *(float2*)(C + (size_t)R * N + col) = v0;
            *(float2*)(C + (size_t)(R + 8) * N + col) = v1;
        }
    }
}

// ---------------------------------------------------------------------------
// Flash attention via mma.sync m16n8k8 tf32 — 4 warps x 32 q-rows.
// (Math identical to Rounds 5-8, passing at rel_err ~6.77e-4 overall.)
// ---------------------------------------------------------------------------
__global__ __launch_bounds__(128, 2)
void flash_mma_kernel(const float* __restrict__ Q, const float* __restrict__ K,
                      const float* __restrict__ V, float* __restrict__ O, int S)
{
    __shared__ uint32_t Kt[64 * 68];
    __shared__ uint32_t Vs[64 * 68];

    const int tid  = threadIdx.x;
    const int wid  = tid >> 5;           // 0..3
    const int lane = tid & 31;
    const int gr   = lane >> 2;
    const int tig  = lane & 3;

    const int q0 = blockIdx.x * 128;
    const int b  = blockIdx.y >> 4;
    const int h  = blockIdx.y & 15;
    const int m0 = wid * 32;             // warp's q-row base within tile

    const float* Qb = Q + ((size_t)b * S + q0) * D_MODEL + h * DK;
    const float* Kb = K + (size_t)b * S * D_MODEL + h * DK;
    const float* Vb = V + (size_t)b * S * D_MODEL + h * DK;

    // Q fragments (2 m16 tiles): fold 1/sqrt(dk) * log2(e) for ex2 softmax.
    const float QSCALE = 0.125f * 1.4426950408889634f;
    uint32_t qf[8][8];
    #pragma unroll
    for (int kk = 0; kk < 8; kk++) {
        const int c0 = kk * 8 + tig;
        qf[kk][0] = f2tf32(Qb[(size_t)(m0 + gr)      * D_MODEL + c0]     * QSCALE);
        qf[kk][1] = f2tf32(Qb[(size_t)(m0 + gr + 8)  * D_MODEL + c0]     * QSCALE);
        qf[kk][2] = f2tf32(Qb[(size_t)(m0 + gr)      * D_MODEL + c0 + 4] * QSCALE);
        qf[kk][3] = f2tf32(Qb[(size_t)(m0 + gr + 8)  * D_MODEL + c0 + 4] * QSCALE);
        qf[kk][4] = f2tf32(Qb[(size_t)(m0 + gr + 16) * D_MODEL + c0]     * QSCALE);
        qf[kk][5] = f2tf32(Qb[(size_t)(m0 + gr + 24) * D_MODEL + c0]     * QSCALE);
        qf[kk][6] = f2tf32(Qb[(size_t)(m0 + gr + 16) * D_MODEL + c0 + 4] * QSCALE);
        qf[kk][7] = f2tf32(Qb[(size_t)(m0 + gr + 24) * D_MODEL + c0 + 4] * QSCALE);
    }

    float m_g[4], l_g[4];
    #pragma unroll
    for (int g = 0; g < 4; g++) { m_g[g] = -1e30f; l_g[g] = 0.0f; }
    float o[8][8];
    #pragma unroll
    for (int nn = 0; nn < 8; nn++)
        #pragma unroll
        for (int j = 0; j < 8; j++) o[nn][j] = 0.0f;

    const int srcA = (lane & 28) | (tig >> 1);  // source lane for col tig
    const int srcB = srcA + 2;                  // source lane for col tig+4
    const bool sel = (tig & 1) != 0;

    const int nkb = S >> 6;
    for (int kb = 0; kb < nkb; kb++) {
        __syncthreads();
        // Cooperative K/V tile load (64 x 64), tf32-rounded, pad-68 rows.
        #pragma unroll
        for (int i = 0; i < 8; i++) {
            int idx = tid + i * 128;
            int r = idx >> 4, c4 = idx & 15;
            float4 k4 = *(const float4*)(Kb + (size_t)(kb*64 + r) * D_MODEL + c4*4);
            uint4 ku; ku.x = f2tf32(k4.x); ku.y = f2tf32(k4.y);
                      ku.z = f2tf32(k4.z); ku.w = f2tf32(k4.w);
            *(uint4*)&Kt[r * 68 + c4 * 4] = ku;
            float4 v4 = *(const float4*)(Vb + (size_t)(kb*64 + r) * D_MODEL + c4*4);
            uint4 vu; vu.x = f2tf32(v4.x); vu.y = f2tf32(v4.y);
                      vu.z = f2tf32(v4.z); vu.w = f2tf32(v4.w);
            *(uint4*)&Vs[r * 68 + c4 * 4] = vu;
        }
        __syncthreads();

        // ---- S = Q @ K^T : warp computes 32 x 64 scores ----
        float sv[8][8];
        #pragma unroll
        for (int nn = 0; nn < 8; nn++) {
            #pragma unroll
            for (int j = 0; j < 8; j++) sv[nn][j] = 0.0f;
            #pragma unroll
            for (int kk = 0; kk < 8; kk++) {
                uint32_t b0 = Kt[(nn*8 + gr) * 68 + kk*8 + tig];
                uint32_t b1 = Kt[(nn*8 + gr) * 68 + kk*8 + tig + 4];
                MMA_TF32(&sv[nn][0], &qf[kk][0], b0, b1);   // rows m0..m0+16
                MMA_TF32(&sv[nn][4], &qf[kk][4], b0, b1);   // rows m0+16..m0+32
            }
        }

        // ---- online softmax: 4 row groups, quad-local reductions ----
        float al[4];
        #pragma unroll
        for (int g = 0; g < 4; g++) {
            float mx = -1e30f;
            #pragma unroll
            for (int nn = 0; nn < 8; nn++)
                mx = fmaxf(mx, fmaxf(sv[nn][2*g], sv[nn][2*g+1]));
            mx = fmaxf(mx, __shfl_xor_sync(0xffffffffu, mx, 1));
            mx = fmaxf(mx, __shfl_xor_sync(0xffffffffu, mx, 2));
            float mn = fmaxf(m_g[g], mx);
            al[g] = ex2f(m_g[g] - mn);
            m_g[g] = mn;
            float rs = 0.0f;
            #pragma unroll
            for (int nn = 0; nn < 8; nn++) {
                sv[nn][2*g]   = ex2f(sv[nn][2*g]   - mn);
                sv[nn][2*g+1] = ex2f(sv[nn][2*g+1] - mn);
                rs += sv[nn][2*g] + sv[nn][2*g+1];
            }
            rs += __shfl_xor_sync(0xffffffffu, rs, 1);
            rs += __shfl_xor_sync(0xffffffffu, rs, 2);
            l_g[g] = l_g[g] * al[g] + rs;
        }
        #pragma unroll
        for (int nn = 0; nn < 8; nn++)
            #pragma unroll
            for (int g = 0; g < 4; g++) {
                o[nn][2*g]   *= al[g];
                o[nn][2*g+1] *= al[g];
            }

        // ---- O += P @ V : P C-frags -> A-frags via shuffles ----
        #pragma unroll
        for (int kk = 0; kk < 8; kk++) {
            uint32_t a[8];
            #pragma unroll
            for (int t = 0; t < 2; t++) {
                float v00 = __shfl_sync(0xffffffffu, sv[kk][t*4+0], srcA);
                float v01 = __shfl_sync(0xffffffffu, sv[kk][t*4+1], srcA);
                float v10 = __shfl_sync(0xffffffffu, sv[kk][t*4+2], srcA);
                float v11 = __shfl_sync(0xffffffffu, sv[kk][t*4+3], srcA);
                float w00 = __shfl_sync(0xffffffffu, sv[kk][t*4+0], srcB);
                float w01 = __shfl_sync(0xffffffffu, sv[kk][t*4+1], srcB);
                float w10 = __shfl_sync(0xffffffffu, sv[kk][t*4+2], srcB);
                float w11 = __shfl_sync(0xffffffffu, sv[kk][t*4+3], srcB);
                a[t*4+0] = __float_as_uint(sel ? v01 : v00);
                a[t*4+1] = __float_as_uint(sel ? v11 : v10);
                a[t*4+2] = __float_as_uint(sel ? w01 : w00);
                a[t*4+3] = __float_as_uint(sel ? w11 : w10);
            }
            #pragma unroll
            for (int nn = 0; nn < 8; nn++) {
                uint32_t b0 = Vs[(kk*8 + tig)     * 68 + nn*8 + gr];
                uint32_t b1 = Vs[(kk*8 + tig + 4) * 68 + nn*8 + gr];
                MMA_TF32(&o[nn][0], &a[0], b0, b1);
                MMA_TF32(&o[nn][4], &a[4], b0, b1);
            }
        }
    }

    // ---- epilogue: normalize, store (layout [B*S, D_MODEL]) ----
    float inv[4];
    #pragma unroll
    for (int g = 0; g < 4; g++) inv[g] = 1.0f / l_g[g];
    float* Ob = O + ((size_t)b * S + q0) * D_MODEL + h * DK;
    const int rowg[4] = { m0 + gr, m0 + gr + 8, m0 + gr + 16, m0 + gr + 24 };
    #pragma unroll
    for (int nn = 0; nn < 8; nn++) {
        #pragma unroll
        for (int g = 0; g < 4; g++) {
            float2 val;
            val.x = o[nn][2*g]   * inv[g];
            val.y = o[nn][2*g+1] * inv[g];
            *(float2*)(Ob + (size_t)rowg[g] * D_MODEL + nn*8 + tig*2) = val;
        }
    }
}

// ---------------------------------------------------------------------------
extern "C" void kernel_launch(void* const* d_in, const int* in_sizes, int n_in,
                              void* d_out, int out_size)
{
    (void)n_in; (void)out_size;
    const float* query = (const float*)d_in[0];
    const float* key   = (const float*)d_in[1];
    const float* value = (const float*)d_in[2];
    const float* Wq = (const float*)d_in[3];
    const float* bq = (const float*)d_in[4];
    const float* Wk = (const float*)d_in[5];
    const float* bk = (const float*)d_in[6];
    const float* Wv = (const float*)d_in[7];
    const float* bv = (const float*)d_in[8];
    const float* Wo = (const float*)d_in[9];
    const float* bo = (const float*)d_in[10];
    float* out = (float*)d_out;

    const int M = in_sizes[0] / D_MODEL;   // B*S = 8192
    const int S = M / BATCH;               // 4096
    const int K2 = D_MODEL / 2;            // 512 packed pairs

    float *pQ, *pK, *pV, *pAO;
    uint32_t *pAhi, *pAlo, *pWhi, *pWlo;
    cudaGetSymbolAddress((void**)&pQ,   g_Q);
    cudaGetSymbolAddress((void**)&pK,   g_K);
    cudaGetSymbolAddress((void**)&pV,   g_V);
    cudaGetSymbolAddress((void**)&pAO,  g_AO);
    cudaGetSymbolAddress((void**)&pAhi, g_Ahi);
    cudaGetSymbolAddress((void**)&pAlo, g_Alo);
    cudaGetSymbolAddress((void**)&pWhi, g_Whi);
    cudaGetSymbolAddress((void**)&pWlo, g_Wlo);

    cudaFuncSetAttribute(gemm_bf16_kernel,
                         cudaFuncAttributeMaxDynamicSharedMemorySize, GEMM_SMEM);

    const int nsplit = M * D_MODEL / 4 / 256;        // 8192 blocks
    const int nw     = D2 / 4 / 256;                 // 1024 blocks per weight
    dim3 gblk(D_MODEL / 128, M / 128);               // (8, 64)

    split_w4_kernel<<<dim3(nw, 4), 256>>>(Wq, Wk, Wv, Wo, pWhi, pWlo);

    split_bf16_kernel<<<nsplit, 256>>>(query, pAhi, pAlo);
    gemm_bf16_kernel<<<gblk, 256, GEMM_SMEM>>>(pAhi, pAlo, pWhi, pWlo,
                                               bq, pQ, M, D_MODEL, K2);
    split_bf16_kernel<<<nsplit, 256>>>(key, pAhi, pAlo);
    gemm_bf16_kernel<<<gblk, 256, GEMM_SMEM>>>(pAhi, pAlo, pWhi + HW, pWlo + HW,
                                               bk, pK, M, D_MODEL, K2);
    split_bf16_kernel<<<nsplit, 256>>>(value, pAhi, pAlo);
    gemm_bf16_kernel<<<gblk, 256, GEMM_SMEM>>>(pAhi, pAlo, pWhi + 2*HW, pWlo + 2*HW,
                                               bv, pV, M, D_MODEL, K2);

    flash_mma_kernel<<<dim3(S / 128, BATCH * N_HEADS), 128>>>(pQ, pK, pV, pAO, S);

    split_bf16_kernel<<<nsplit, 256>>>(pAO, pAhi, pAlo);
    gemm_bf16_kernel<<<gblk, 256, GEMM_SMEM>>>(pAhi, pAlo, pWhi + 3*HW, pWlo + 3*HW,
                                               bo, out, M, D_MODEL, K2);
}